// round 10
// baseline (speedup 1.0000x reference)
#include <cuda_runtime.h>
#include <cstdint>

#define BATCH   32768
#define NUM_IN  256
#define NUM_HID 512
#define NUM_OUT 64
#define M_NODES 576
#define N_NODES 832
#define KFAN    32
#define COLS    64             // batch columns per block (fp32, lane owns 2)
#define WPN     64             // f32 words per node row
#define THREADS 1024           // 32 warps
#define CAP     32             // max nodes per round (warp per node)
#define NSTRIDE 68             // words/slot: 32 w + 32 src(u32 premul) + bias + tgt + 2 pad
#define RSTRIDE (CAP * NSTRIDE)   // 2176 words = 8704 B per round
#define RMAX_R  576
#define DUMMY   576            // dummy pred index for scheduler, level pinned 0

// blob: slot i of round r at r*RSTRIDE + i*NSTRIDE:
//   [0..32) w, [32..64) src offsets (u32, premultiplied by WPN),
//   [64] bias, [65] target word-offset (int), [66] (slot 0 only) round width rc
__device__ float g_blob[(size_t)RMAX_R * RSTRIDE];
__device__ int   g_sched[RMAX_R * CAP];
__device__ int   g_rcnt[RMAX_R];
__device__ int   g_nrounds;

// ---------------------------------------------------------------------------
// Kernel A (R6-proven): ASAP levels via chunked Gauss-Seidel, preds in
// registers (DUMMY-padded), then counting-sort into rounds of <= CAP.
// ---------------------------------------------------------------------------
__global__ __launch_bounds__(M_NODES)
void schedule_kernel(const int* __restrict__ src) {
    __shared__ int lev[DUMMY + 32];       // lev[DUMMY..] pinned 0
    __shared__ int cnt[M_NODES + 1];
    __shared__ int lbase[M_NODES + 1];
    __shared__ int pos[M_NODES + 1];
    __shared__ int flag, lmax;

    const int t = threadIdx.x;

    int p[KFAN];
    #pragma unroll
    for (int k = 0; k < KFAN; k++) {
        int s = src[t * KFAN + k];
        p[k] = (s >= NUM_IN) ? (s - NUM_IN) : DUMMY;
    }
    lev[t] = 0;
    if (t < 32) lev[DUMMY + t] = 0;
    for (int i = t; i <= M_NODES; i += M_NODES) { cnt[i] = 0; pos[i] = 0; }
    if (t == 0) lmax = 0;
    __syncthreads();

    // 9 chunks of 64 consecutive nodes; preds strictly lower-indexed
    for (int c = 0; c < M_NODES / 64; c++) {
        const bool mine = ((t >> 6) == c);
        while (true) {
            if (t == 0) flag = 0;
            __syncthreads();
            if (mine) {
                int m = 0;
                #pragma unroll
                for (int k = 0; k < KFAN; k++) {
                    int l = lev[p[k]];
                    m = (l > m) ? l : m;
                }
                if (m + 1 != lev[t]) { lev[t] = m + 1; flag = 1; }
            }
            __syncthreads();
            if (!flag) break;
        }
    }

    atomicAdd(&cnt[lev[t]], 1);
    atomicMax(&lmax, lev[t]);
    __syncthreads();

    if (t == 0) {
        int R = 0;
        for (int L = 1; L <= lmax; L++) {
            lbase[L] = R;
            int wL = cnt[L];
            while (wL > 0) {                       // split wide levels
                g_rcnt[R] = (wL < CAP) ? wL : CAP;
                wL -= CAP;
                R++;
            }
        }
        g_nrounds = R;
    }
    __syncthreads();

    {
        int L = lev[t];
        int q = atomicAdd(&pos[L], 1);
        g_sched[(lbase[L] + q / CAP) * CAP + (q % CAP)] = t;
    }
}

// ---------------------------------------------------------------------------
// Kernel B: blob fill — one block per round, 256 threads, parallel slots.
// ---------------------------------------------------------------------------
__global__ __launch_bounds__(256)
void blob_fill_kernel(const int* __restrict__ src,
                      const float* __restrict__ w,
                      const float* __restrict__ bias) {
    const int r = blockIdx.x;
    if (r >= g_nrounds) return;
    const int rc = g_rcnt[r];
    float* Pr = g_blob + (size_t)r * RSTRIDE;
    const int tid = threadIdx.x;

    // w: 32 slots x 32 weights = 1024 words
    #pragma unroll
    for (int u = 0; u < 4; u++) {
        int q = tid + u * 256;
        int slot = q >> 5, k = q & 31;
        int nd = (slot < rc) ? g_sched[r * CAP + slot] : -1;
        Pr[slot * NSTRIDE + k] = (nd >= 0) ? w[nd * KFAN + k] : 0.0f;
    }
    // src offsets: 32 slots x 32 preds, premultiplied by WPN
    #pragma unroll
    for (int u = 0; u < 4; u++) {
        int q = tid + u * 256;
        int slot = q >> 5, k = q & 31;
        int nd = (slot < rc) ? g_sched[r * CAP + slot] : -1;
        ((unsigned*)Pr)[slot * NSTRIDE + 32 + k] =
            (nd >= 0) ? (unsigned)src[nd * KFAN + k] * WPN : 0u;
    }
    // bias + target + rc
    if (tid < CAP) {
        int nd = (tid < rc) ? g_sched[r * CAP + tid] : -1;
        Pr[tid * NSTRIDE + 64] = (nd >= 0) ? bias[nd] : 0.0f;
        ((int*)Pr)[tid * NSTRIDE + 65] = (nd >= 0) ? (NUM_IN + nd) * WPN : -1;
    }
    if (tid == 0) ((int*)Pr)[66] = rc;             // round width in slot 0 pad
}

// ---------------------------------------------------------------------------
// Main kernel: 512 blocks x 1024 threads, 1 block/SM. fp32 state in SMEM,
// warp per node, variable-width rounds, params double-buffered via cp.async.
// ---------------------------------------------------------------------------
#define ST_WORDS    (N_NODES * WPN)                // 53248
#define PBUF_WORDS  (2 * RSTRIDE)                  // 4352 (covers 64x33 staging)
#define TOTAL_WORDS (ST_WORDS + PBUF_WORDS)        // 57600 -> 230400 B

extern __shared__ float smem_f[];

__device__ __forceinline__ void cp16(void* sdst, const void* gsrc) {
    uint32_t s = (uint32_t)__cvta_generic_to_shared(sdst);
    asm volatile("cp.async.cg.shared.global [%0], [%1], 16;\n" :: "r"(s), "l"(gsrc));
}

__global__ __launch_bounds__(THREADS, 1)
void neat_main_kernel(const float* __restrict__ x,
                      float* __restrict__ out) {
    float* st    = smem_f;                         // [N_NODES][WPN]
    float* stage = smem_f + ST_WORDS;              // param double buffer / staging

    const int tid  = threadIdx.x;
    const int wid  = tid >> 5;
    const int lane = tid & 31;
    const int b0   = blockIdx.x * COLS;
    const int R    = g_nrounds;

    // ---- input transpose: x[b][n] -> st[n][col]; 8 chunks of 32 inputs ----
    for (int ch = 0; ch < 8; ch++) {
        const int nc0 = ch * 32;
        __syncthreads();
        #pragma unroll
        for (int i = 0; i < 2; i++) {
            int idx = tid + i * THREADS;           // 2048 = 64 rows x 32 cols
            int row = idx >> 5, c = idx & 31;
            stage[row * 33 + c] = x[(size_t)(b0 + row) * NUM_IN + nc0 + c];
        }
        __syncthreads();
        #pragma unroll
        for (int i = 0; i < 2; i++) {
            int idx = tid + i * THREADS;           // 2048 = 32 nodes x 64 cols
            int n = idx >> 6, col = idx & 63;
            st[(nc0 + n) * WPN + col] = stage[col * 33 + n];
        }
    }
    __syncthreads();

    // ---- prefetch round 0 params (2176 words = 544 x 16B) ----
    if (tid < RSTRIDE / 4) cp16(stage + tid * 4, g_blob + tid * 4);
    asm volatile("cp.async.commit_group;\n");
    asm volatile("cp.async.wait_group 0;\n" ::: "memory");
    __syncthreads();

    float* stc = st + 2 * lane;                    // lane owns cols (2l, 2l+1)

    // ---- main rounds: warp wid evaluates slot wid (if wid < rc) ----
    for (int r = 0; r < R; r++) {
        float* P  = stage + (r & 1) * RSTRIDE;
        float* Pn = stage + ((r + 1) & 1) * RSTRIDE;
        if (r + 1 < R && tid < RSTRIDE / 4)
            cp16(Pn + tid * 4, g_blob + (size_t)(r + 1) * RSTRIDE + tid * 4);
        asm volatile("cp.async.commit_group;\n");

        const int rc = ((const int*)P)[66];
        if (wid < rc) {
            const float* Pp = P + wid * NSTRIDE;
            const float4* wp = (const float4*)Pp;
            const uint4*  sp = (const uint4*)((const unsigned*)Pp + 32);
            const float  bt  = Pp[64];
            const int    tgt = ((const int*)Pp)[65];

            float a0 = 0.f, a1 = 0.f, b0a = 0.f, b1a = 0.f;
            #pragma unroll
            for (int q = 0; q < 8; q++) {
                uint4  u  = sp[q];                 // 4 premultiplied offsets
                float4 w4 = wp[q];
                float2 v0 = *(const float2*)(stc + u.x);
                float2 v1 = *(const float2*)(stc + u.y);
                float2 v2 = *(const float2*)(stc + u.z);
                float2 v3 = *(const float2*)(stc + u.w);
                a0  = fmaf(v0.x, w4.x, a0);  a1  = fmaf(v0.y, w4.x, a1);
                b0a = fmaf(v1.x, w4.y, b0a); b1a = fmaf(v1.y, w4.y, b1a);
                a0  = fmaf(v2.x, w4.z, a0);  a1  = fmaf(v2.y, w4.z, a1);
                b0a = fmaf(v3.x, w4.w, b0a); b1a = fmaf(v3.y, w4.w, b1a);
            }
            float z0 = (a0 + b0a) + bt;
            float z1 = (a1 + b1a) + bt;
            float o0 = __fdividef(1.0f, 1.0f + __expf(-z0));
            float o1 = __fdividef(1.0f, 1.0f + __expf(-z1));
            *(float2*)(stc + tgt) = make_float2(o0, o1);
        }

        asm volatile("cp.async.wait_group 0;\n" ::: "memory");
        __syncthreads();
    }

    // ---- output: out[b][j] = st[768+j][col]; 2 chunks of 32 outputs ----
    for (int ch = 0; ch < 2; ch++) {
        const int j0 = ch * 32;
        __syncthreads();
        #pragma unroll
        for (int i = 0; i < 2; i++) {
            int idx = tid + i * THREADS;           // 2048 = 32 j x 64 cols
            int j = idx >> 6, col = idx & 63;
            stage[col * 33 + j] = st[(NUM_IN + NUM_HID + j0 + j) * WPN + col];
        }
        __syncthreads();
        #pragma unroll
        for (int i = 0; i < 2; i++) {
            int idx = tid + i * THREADS;           // 2048 = 64 rows x 32 j
            int row = idx >> 5, j = idx & 31;
            out[(size_t)(b0 + row) * NUM_OUT + j0 + j] = stage[row * 33 + j];
        }
    }
}

// ---------------------------------------------------------------------------
extern "C" void kernel_launch(void* const* d_in, const int* in_sizes, int n_in,
                              void* d_out, int out_size) {
    const float* x    = (const float*)d_in[0];
    const float* w    = (const float*)d_in[1];
    const float* bias = (const float*)d_in[2];
    const int*   src  = (const int*)d_in[3];
    float* out = (float*)d_out;
    (void)in_sizes; (void)n_in; (void)out_size;

    cudaFuncSetAttribute(neat_main_kernel,
                         cudaFuncAttributeMaxDynamicSharedMemorySize,
                         TOTAL_WORDS * 4);

    schedule_kernel<<<1, M_NODES>>>(src);
    blob_fill_kernel<<<RMAX_R, 256>>>(src, w, bias);
    neat_main_kernel<<<BATCH / COLS, THREADS, TOTAL_WORDS * 4>>>(x, out);
}

// round 11
// speedup vs baseline: 1.6939x; 1.6939x over previous
#include <cuda_runtime.h>
#include <cuda_fp16.h>
#include <cstdint>

#define BATCH   32768
#define NUM_IN  256
#define NUM_HID 512
#define NUM_OUT 64
#define M_NODES 576
#define N_NODES 832
#define KFAN    32
#define COLS    64             // batch columns per block (32 half2 words)
#define WPN     32             // u32 words per node row
#define THREADS 512            // 16 warps
#define SLOTS   16             // nodes per round (1 per warp)
#define RSTRIDE 800            // words/round: 256 src16 + 512 w_h2 + 16 bias + 16 tgt
#define RMAX    576
#define DUMMY   576            // dummy pred index, level pinned 0

// round-major param blob, per round r at r*RSTRIDE:
//   [0..256)      src16: two u16 (pred*WPN) word-offsets per u32 (slot*16 + j)
//   [256..768)    w_h2:  u32 = half2 {w,w}        (256 + slot*32 + k)
//   [768..784)    bias per slot (f32)
//   [784..800)    target word-offset per slot (int), -1 = dummy
__device__ float g_blob[(size_t)RMAX * RSTRIDE];
__device__ int   g_sched[RMAX * SLOTS];
__device__ int   g_nrounds;

// ---------------------------------------------------------------------------
// Kernel A: ASAP levels via chunked Gauss-Seidel (preds in registers,
// DUMMY-padded), one fused barrier per pass via __syncthreads_or;
// then counting-sort levels into rounds of <= SLOTS.
// ---------------------------------------------------------------------------
__global__ __launch_bounds__(M_NODES)
void schedule_kernel(const int* __restrict__ src) {
    __shared__ int lev[DUMMY + 32];       // lev[DUMMY..] pinned 0
    __shared__ int cnt[M_NODES + 1];
    __shared__ int rbase[M_NODES + 1];
    __shared__ int pos[M_NODES + 1];
    __shared__ int lmax, R_sh;

    const int t = threadIdx.x;

    int p[KFAN];
    #pragma unroll
    for (int k = 0; k < KFAN; k++) {
        int s = src[t * KFAN + k];
        p[k] = (s >= NUM_IN) ? (s - NUM_IN) : DUMMY;
    }
    lev[t] = 0;
    if (t < 32) lev[DUMMY + t] = 0;
    for (int i = t; i <= M_NODES; i += M_NODES) { cnt[i] = 0; pos[i] = 0; }
    if (t == 0) lmax = 0;
    __syncthreads();

    // 9 chunks of 64 consecutive nodes; preds strictly lower-indexed.
    for (int c = 0; c < M_NODES / 64; c++) {
        const bool mine = ((t >> 6) == c);
        while (true) {
            int ch = 0;
            if (mine) {
                int m = 0;
                #pragma unroll
                for (int k = 0; k < KFAN; k++) {
                    int l = lev[p[k]];
                    m = (l > m) ? l : m;
                }
                if (m + 1 != lev[t]) { lev[t] = m + 1; ch = 1; }
            }
            if (!__syncthreads_or(ch)) break;
        }
    }

    atomicAdd(&cnt[lev[t]], 1);
    atomicMax(&lmax, lev[t]);
    __syncthreads();

    if (t == 0) {
        int r = 0;
        for (int L = 1; L <= lmax; L++) { rbase[L] = r; r += (cnt[L] + SLOTS - 1) >> 4; }
        R_sh = r;
        g_nrounds = r;
    }
    __syncthreads();

    for (int i = t; i < R_sh * SLOTS; i += M_NODES) g_sched[i] = -1;
    __syncthreads();

    {
        int L = lev[t];
        int q = atomicAdd(&pos[L], 1);
        g_sched[(rbase[L] + (q >> 4)) * SLOTS + (q & 15)] = t;
    }
}

// ---------------------------------------------------------------------------
// Kernel B: grid-parallel blob fill, one block per (used) round.
// ---------------------------------------------------------------------------
__global__ __launch_bounds__(256)
void blob_fill_kernel(const int* __restrict__ src,
                      const float* __restrict__ w,
                      const float* __restrict__ bias) {
    const int r = blockIdx.x;
    if (r >= g_nrounds) return;
    float* Pr = g_blob + (size_t)r * RSTRIDE;
    const int tid = threadIdx.x;

    // src16: 256 words, premultiplied (pred * WPN) offsets
    {
        int slot = tid >> 4, j = tid & 15;
        int nd = g_sched[r * SLOTS + slot];
        unsigned v = 0;
        if (nd >= 0) {
            unsigned a = (unsigned)src[nd * KFAN + 2 * j] * WPN;
            unsigned b = (unsigned)src[nd * KFAN + 2 * j + 1] * WPN;
            v = (a & 0xFFFFu) | (b << 16);
        }
        ((unsigned*)Pr)[slot * 16 + j] = v;
    }
    // w_h2: 512 words, each = half2 {w, w}
    #pragma unroll
    for (int u = 0; u < 2; u++) {
        int q = tid + u * 256;
        int slot = q >> 5, k = q & 31;
        int nd = g_sched[r * SLOTS + slot];
        float wv = (nd >= 0) ? w[nd * KFAN + k] : 0.0f;
        __half  h  = __float2half_rn(wv);
        __half2 h2 = __half2half2(h);
        ((uint32_t*)Pr)[256 + slot * 32 + k] = *(uint32_t*)&h2;
    }
    // bias + target
    if (tid < SLOTS) {
        int nd = g_sched[r * SLOTS + tid];
        Pr[768 + tid] = (nd >= 0) ? bias[nd] : 0.0f;
        ((int*)Pr)[784 + tid] = (nd >= 0) ? (NUM_IN + nd) * WPN : -1;
    }
}

// ---------------------------------------------------------------------------
// Main kernel: 512 blocks x 512 threads, 2 blocks/SM. State half2-packed in
// SMEM; HFMA2 inner product (4 chains), f32 flush every 16 preds, fp32
// sigmoid. Params double-buffered via cp.async.
// ---------------------------------------------------------------------------
#define ST_WORDS    (N_NODES * WPN)                // 26624 u32
#define STAGE_WORDS 2112                           // 64x33 f32 staging >= 2*RSTRIDE
#define TOTAL_WORDS (ST_WORDS + STAGE_WORDS)       // 28736 -> 114944 B

extern __shared__ float smem_f[];

__device__ __forceinline__ void cp16(void* sdst, const void* gsrc) {
    uint32_t s = (uint32_t)__cvta_generic_to_shared(sdst);
    asm volatile("cp.async.cg.shared.global [%0], [%1], 16;\n" :: "r"(s), "l"(gsrc));
}

__device__ __forceinline__ __half2 u2h(uint32_t u) { return *(__half2*)&u; }

__global__ __launch_bounds__(THREADS, 2)
void neat_main_kernel(const float* __restrict__ x,
                      float* __restrict__ out) {
    uint32_t* st   = (uint32_t*)smem_f;            // [N_NODES][WPN] half2 words
    float*   stage = smem_f + ST_WORDS;            // staging / param double buffer

    const int tid  = threadIdx.x;
    const int wid  = tid >> 5;
    const int lane = tid & 31;
    const int b0   = blockIdx.x * COLS;
    const int R    = g_nrounds;

    // ---- input: x[b][n] f32 -> st[n] half2-packed; 8 chunks of 32 inputs ----
    for (int ch = 0; ch < 8; ch++) {
        const int nc0 = ch * 32;
        __syncthreads();
        #pragma unroll
        for (int i = 0; i < 4; i++) {
            int idx = tid + i * THREADS;           // 2048 = 64 rows x 32 cols
            int row = idx >> 5, c = idx & 31;
            stage[row * 33 + c] = x[(size_t)(b0 + row) * NUM_IN + nc0 + c];
        }
        __syncthreads();
        #pragma unroll
        for (int i = 0; i < 2; i++) {
            int idx = tid + i * THREADS;           // 1024 = 32 nodes x 32 words
            int n = idx >> 5, wc = idx & 31;
            float lo = stage[(2 * wc) * 33 + n];
            float hi = stage[(2 * wc + 1) * 33 + n];
            __half2 h = __floats2half2_rn(lo, hi);
            st[(nc0 + n) * WPN + wc] = *(uint32_t*)&h;
        }
    }
    __syncthreads();

    // ---- prefetch round 0 params ----
    if (tid < RSTRIDE / 4) cp16(stage + tid * 4, g_blob + tid * 4);
    asm volatile("cp.async.commit_group;\n");
    asm volatile("cp.async.wait_group 0;\n" ::: "memory");
    __syncthreads();

    uint32_t* stc = st + lane;                     // lane owns cols (2l, 2l+1)

    // ---- main rounds: warp wid evaluates slot wid over 64 columns ----
    for (int r = 0; r < R; r++) {
        float* P  = stage + (r & 1) * RSTRIDE;
        float* Pn = stage + ((r + 1) & 1) * RSTRIDE;
        if (r + 1 < R && tid < RSTRIDE / 4)
            cp16(Pn + tid * 4, g_blob + (size_t)(r + 1) * RSTRIDE + tid * 4);
        asm volatile("cp.async.commit_group;\n");

        const int tgt = ((const int*)P)[784 + wid];
        if (tgt >= 0) {
            const uint4* s4 = (const uint4*)((const unsigned*)P + wid * 16);
            const uint4* w4 = (const uint4*)((const uint32_t*)P + 256 + wid * 32);
            const float  bt = P[768 + wid];

            float z0 = bt, z1 = bt;
            #pragma unroll
            for (int half = 0; half < 2; half++) { // 16 preds per flush group
                __half2 A = __float2half2_rn(0.f);
                __half2 B = __float2half2_rn(0.f);
                __half2 C = __float2half2_rn(0.f);
                __half2 D = __float2half2_rn(0.f);
                #pragma unroll
                for (int h = 0; h < 2; h++) {      // 8 preds per iter
                    uint4 u  = s4[half * 2 + h];
                    uint4 wa = w4[half * 4 + h * 2];
                    uint4 wb = w4[half * 4 + h * 2 + 1];
                    uint32_t v0 = stc[u.x & 0xFFFFu];
                    uint32_t v1 = stc[u.x >> 16];
                    uint32_t v2 = stc[u.y & 0xFFFFu];
                    uint32_t v3 = stc[u.y >> 16];
                    uint32_t v4 = stc[u.z & 0xFFFFu];
                    uint32_t v5 = stc[u.z >> 16];
                    uint32_t v6 = stc[u.w & 0xFFFFu];
                    uint32_t v7 = stc[u.w >> 16];
                    A = __hfma2(u2h(v0), u2h(wa.x), A);
                    B = __hfma2(u2h(v1), u2h(wa.y), B);
                    C = __hfma2(u2h(v2), u2h(wa.z), C);
                    D = __hfma2(u2h(v3), u2h(wa.w), D);
                    A = __hfma2(u2h(v4), u2h(wb.x), A);
                    B = __hfma2(u2h(v5), u2h(wb.y), B);
                    C = __hfma2(u2h(v6), u2h(wb.z), C);
                    D = __hfma2(u2h(v7), u2h(wb.w), D);
                }
                __half2 s = __hadd2(__hadd2(A, B), __hadd2(C, D));
                float2  f = __half22float2(s);
                z0 += f.x;
                z1 += f.y;
            }
            float o0 = __fdividef(1.0f, 1.0f + __expf(-z0));
            float o1 = __fdividef(1.0f, 1.0f + __expf(-z1));
            __half2 hres = __floats2half2_rn(o0, o1);
            stc[tgt] = *(uint32_t*)&hres;
        }

        asm volatile("cp.async.wait_group 0;\n" ::: "memory");
        __syncthreads();
    }

    // ---- output: out[b][j] f32; 2 chunks of 32 output nodes ----
    for (int ch = 0; ch < 2; ch++) {
        const int j0 = ch * 32;
        __syncthreads();
        #pragma unroll
        for (int i = 0; i < 2; i++) {
            int idx = tid + i * THREADS;           // 1024 = 32 j x 32 words
            int j = idx >> 5, wc = idx & 31;
            uint32_t u = st[(NUM_IN + NUM_HID + j0 + j) * WPN + wc];
            float2 v = __half22float2(*(__half2*)&u);
            stage[(2 * wc) * 33 + j]     = v.x;
            stage[(2 * wc + 1) * 33 + j] = v.y;
        }
        __syncthreads();
        #pragma unroll
        for (int i = 0; i < 4; i++) {
            int idx = tid + i * THREADS;           // 2048 = 64 rows x 32 j
            int row = idx >> 5, j = idx & 31;
            out[(size_t)(b0 + row) * NUM_OUT + j0 + j] = stage[row * 33 + j];
        }
    }
}

// ---------------------------------------------------------------------------
extern "C" void kernel_launch(void* const* d_in, const int* in_sizes, int n_in,
                              void* d_out, int out_size) {
    const float* x    = (const float*)d_in[0];
    const float* w    = (const float*)d_in[1];
    const float* bias = (const float*)d_in[2];
    const int*   src  = (const int*)d_in[3];
    float* out = (float*)d_out;
    (void)in_sizes; (void)n_in; (void)out_size;

    cudaFuncSetAttribute(neat_main_kernel,
                         cudaFuncAttributeMaxDynamicSharedMemorySize,
                         TOTAL_WORDS * 4);

    schedule_kernel<<<1, M_NODES>>>(src);
    blob_fill_kernel<<<RMAX, 256>>>(src, w, bias);
    neat_main_kernel<<<BATCH / COLS, THREADS, TOTAL_WORDS * 4>>>(x, out);
}